// round 17
// baseline (speedup 1.0000x reference)
#include <cuda_runtime.h>
#include <cstdint>

// ============================================================================
// out[524288,128] = x @ P^T, P = Sinkhorn(exp(clip((logits+gumbel(u))/3)))
// Fused persistent kernel. FULLY WARP-INDEPENDENT pipelines (R14/R16 base):
//   R17: 384 threads = 12 warps = 6 bands x 2 twins {w, w+6}.
//   - 3 slots/warp (depth-3 cp.async pipeline, ~720cyc lead > DRAM ~577) --
//     R16's depth-2 gave only ~480cyc, exposing DRAM tail every wait_group
//   - reg cap 65536/384 = 170 (R16 was pinned at exactly 128 -> no ptxas
//     headroom to hoist LDS across MMA bursts)
//   - PF float4 fragment order (R16 win), zero mainloop sync, warp tile m32n64
// (tcgen05 unavailable: harness targets compute_103, not 103a.)
// ============================================================================

#define EPSF 1e-20f

__device__ __forceinline__ uint32_t smem_u32(const void* p) {
    uint32_t a;
    asm("{ .reg .u64 t; cvta.to.shared.u64 t, %1; cvt.u32.u64 %0, t; }" : "=r"(a) : "l"(p));
    return a;
}
__device__ __forceinline__ void cp16(float* dst, const float* src) {
    uint32_t d = smem_u32(dst);
    asm volatile("cp.async.cg.shared.global [%0], [%1], 16;" :: "r"(d), "l"(src) : "memory");
}
__device__ __forceinline__ void cp_commit() { asm volatile("cp.async.commit_group;" ::: "memory"); }
__device__ __forceinline__ void cp_wait0()  { asm volatile("cp.async.wait_group 0;" ::: "memory"); }
__device__ __forceinline__ void cp_wait1()  { asm volatile("cp.async.wait_group 1;" ::: "memory"); }
__device__ __forceinline__ void cp_wait2()  { asm volatile("cp.async.wait_group 2;" ::: "memory"); }

// smem plan: PF 16384 f | SLOTS 12 warps * 3 * 1024 f | Rv,Cv 256 f
static constexpr int PF_FLOATS   = 16384;
static constexpr int SLOT_FLOATS = 1024;                 // 32 rows x 32 cols
static constexpr int SLOTS_TOTAL = 12 * 3 * SLOT_FLOATS; // 36864
static constexpr int SMEM_BYTES  = (PF_FLOATS + SLOTS_TOTAL + 256) * 4;  // 214016

// swizzled float offset within a 32x32 slot: row 0..31, c4 = 16B chunk 0..7
__device__ __forceinline__ int soff(int row, int c4) {
    return row * 32 + (((c4) ^ (row & 7)) << 2);
}

__global__ void __launch_bounds__(384, 1)
fused_kernel(const float* __restrict__ x,
             const float* __restrict__ logits,
             const float* __restrict__ u,
             float* __restrict__ out, int nbands) {
    extern __shared__ float sh[];
    float*  PF    = sh;
    float*  SLOTS = sh + PF_FLOATS;
    float*  Rv    = SLOTS + SLOTS_TOTAL;   // 128
    float*  Cv    = Rv + 128;              // 128
    float4* PF4   = reinterpret_cast<float4*>(PF);

    const int tid  = threadIdx.x;
    const int lane = tid & 31;
    const int wid  = tid >> 5;             // 0..11
    const int wb   = (wid < 6) ? wid : (wid - 6);   // band slot within CTA 0..5
    const int wn   = (wid < 6) ? 0 : 1;             // n-half

    float* S0 = SLOTS + wid * 3 * SLOT_FLOATS;
    float* S1 = S0 + SLOT_FLOATS;
    float* S2 = S1 + SLOT_FLOATS;

    // ================= sinkhorn prologue (256-thread scheme, 384-guarded) ====
    {
        float* A = SLOTS;   // 16384-float scratch (slots region, pre-mainloop)
        for (int idx = tid; idx < 16384; idx += 384) {
            float uv = u[idx];
            float g  = -logf(-logf(uv + EPSF) + EPSF);
            float la = (logits[idx] + g) * (1.0f / 3.0f);
            la = fminf(10.0f, fmaxf(-10.0f, la));
            A[idx] = expf(la);
        }
        if (tid < 128) Cv[tid] = 1.0f;
        __syncthreads();

        const int i = tid >> 1;     // row/col 0..127 (tid<256 only)
        const int s = tid & 1;

        float4 a4[16];
        float  at[64];
        if (tid < 256) {
#pragma unroll
            for (int k = 0; k < 16; k++)
                a4[k] = *reinterpret_cast<const float4*>(&A[i * 128 + s * 64 + k * 4]);
#pragma unroll
            for (int j = 0; j < 64; j++)
                at[j] = A[(s * 64 + j) * 128 + i];
        }

        for (int it = 0; it < 20; it++) {
            if (tid < 256) {
                float sum = 0.0f;
#pragma unroll
                for (int k = 0; k < 16; k++) {
                    float4 cv = *reinterpret_cast<const float4*>(&Cv[s * 64 + k * 4]);
                    sum += a4[k].x * cv.x + a4[k].y * cv.y + a4[k].z * cv.z + a4[k].w * cv.w;
                }
                sum += __shfl_xor_sync(0xffffffffu, sum, 1);
                if (s == 0) Rv[i] = 1.0f / sum;
            }
            __syncthreads();

            if (tid < 256) {
                float sum2 = 0.0f;
#pragma unroll
                for (int j = 0; j < 64; j += 4) {
                    float4 rv = *reinterpret_cast<const float4*>(&Rv[s * 64 + j]);
                    sum2 += at[j] * rv.x + at[j + 1] * rv.y +
                            at[j + 2] * rv.z + at[j + 3] * rv.w;
                }
                sum2 += __shfl_xor_sync(0xffffffffu, sum2, 1);
                if (s == 0) Cv[i] = 1.0f / sum2;
            }
            __syncthreads();
        }

        // P = diag(r) A diag(c) * (1+2^-11) [mma RZ-truncation compensation],
        // tf32-rounded, scattered into FLOAT4 B-fragment order (R16 layout):
        //   PF4[(ss*8 + (ntg>>1))*32 + (n&7)*4 + (ko&3)]
        //     element (ntg&1)*2 + (ko>>2);  ntg = n>>3, ss = k>>3, ko = k&7
        const float comp = 1.0f + 0.00048828125f;
        for (int idx = tid; idx < 16384; idx += 384) {
            int n = idx >> 7, k = idx & 127;
            float p = Rv[n] * A[n * 128 + k] * Cv[k] * comp;
            float pt32;
            asm("cvt.rna.tf32.f32 %0, %1;" : "=f"(pt32) : "f"(p));
            int ss = k >> 3, ko = k & 7, ntg = n >> 3;
            int fi = (((ss * 8 + (ntg >> 1)) * 32 + (n & 7) * 4 + (ko & 3)) << 2)
                     + ((ntg & 1) << 1) + (ko >> 2);
            PF[fi] = pt32;
        }
        __syncthreads();   // PF ready; slots free. LAST barrier of the kernel.
    }

    // ================= per-warp independent mainloop ==========================
    const int NW = gridDim.x * 6;                        // bands per pass
    const int gw = blockIdx.x * 6 + wb;                  // this warp's band
    if (gw >= nbands) return;

    // fill one k-quarter (32 rows x 32 cols) of band B into SLOT (8 cp16/thread)
#define ISSUE_Q(SLOT, B, KQ)                                                     \
    {                                                                            \
        const float* srcb = x + (size_t)(B) * 32 * 128 + (KQ) * 32;              \
        _Pragma("unroll")                                                        \
        for (int i = 0; i < 8; i++) {                                            \
            int f = i * 32 + lane;                                               \
            int row = f >> 3, c4 = f & 7;                                        \
            cp16((SLOT) + soff(row, c4), srcb + (size_t)row * 128 + c4 * 4);     \
        }                                                                        \
    }

// compute 4 k-steps of quarter KQ from SLOT into acc (B via LDS.128, R16)
#define COMPUTE_Q(SLOT, KQ)                                                       \
        _Pragma("unroll")                                                         \
        for (int s4 = 0; s4 < 4; s4++) {                                          \
            int s = (KQ) * 4 + s4;                                                \
            float4 bq[4];                                                         \
            _Pragma("unroll")                                                     \
            for (int np = 0; np < 4; np++)                                        \
                bq[np] = PF4[(s * 8 + wn * 4 + np) * 32 + lane];                  \
            _Pragma("unroll")                                                     \
            for (int mf = 0; mf < 2; mf++) {                                      \
                int rq = mf * 16 + (lane >> 2);                                   \
                int w4 = lane & 3;                                                \
                int bc = s4 * 2;                                                  \
                uint32_t a0 = __float_as_uint((SLOT)[soff(rq,     bc    ) + w4]); \
                uint32_t a1 = __float_as_uint((SLOT)[soff(rq + 8, bc    ) + w4]); \
                uint32_t a2 = __float_as_uint((SLOT)[soff(rq,     bc + 1) + w4]); \
                uint32_t a3 = __float_as_uint((SLOT)[soff(rq + 8, bc + 1) + w4]); \
                _Pragma("unroll")                                                 \
                for (int np = 0; np < 4; np++) {                                  \
                    asm volatile(                                                 \
                        "mma.sync.aligned.m16n8k8.row.col.f32.tf32.tf32.f32 "     \
                        "{%0,%1,%2,%3}, {%4,%5,%6,%7}, {%8,%9}, {%0,%1,%2,%3};"   \
                        : "+f"(acc[mf][2*np][0]), "+f"(acc[mf][2*np][1]),         \
                          "+f"(acc[mf][2*np][2]), "+f"(acc[mf][2*np][3])          \
                        : "r"(a0), "r"(a1), "r"(a2), "r"(a3),                     \
                          "r"(__float_as_uint(bq[np].x)),                         \
                          "r"(__float_as_uint(bq[np].y)));                        \
                    asm volatile(                                                 \
                        "mma.sync.aligned.m16n8k8.row.col.f32.tf32.tf32.f32 "     \
                        "{%0,%1,%2,%3}, {%4,%5,%6,%7}, {%8,%9}, {%0,%1,%2,%3};"   \
                        : "+f"(acc[mf][2*np+1][0]), "+f"(acc[mf][2*np+1][1]),     \
                          "+f"(acc[mf][2*np+1][2]), "+f"(acc[mf][2*np+1][3])      \
                        : "r"(a0), "r"(a1), "r"(a2), "r"(a3),                     \
                          "r"(__float_as_uint(bq[np].z)),                         \
                          "r"(__float_as_uint(bq[np].w)));                        \
                }                                                                 \
            }                                                                     \
        }

    // preload quarters 0,1,2 of band gw (3 groups outstanding from here on)
    float *P0 = S0, *P1 = S1, *P2 = S2;
    ISSUE_Q(P0, gw, 0); cp_commit();
    ISSUE_Q(P1, gw, 1); cp_commit();
    ISSUE_Q(P2, gw, 2); cp_commit();

    for (int b = gw; b < nbands; b += NW) {
        const int  bn   = b + NW;
        const bool more = bn < nbands;

        float acc[2][8][4];
#pragma unroll
        for (int mf = 0; mf < 2; mf++)
#pragma unroll
            for (int nt = 0; nt < 8; nt++)
#pragma unroll
                for (int q = 0; q < 4; q++) acc[mf][nt][q] = 0.0f;

        // quarter 0 (slot P0): after compute, refill P0 with this band's q3
        cp_wait2();  COMPUTE_Q(P0, 0)
        ISSUE_Q(P0, b, 3); cp_commit();

        if (more) {
            cp_wait2();  COMPUTE_Q(P1, 1)
            ISSUE_Q(P1, bn, 0); cp_commit();
            cp_wait2();  COMPUTE_Q(P2, 2)
            ISSUE_Q(P2, bn, 1); cp_commit();
            cp_wait2();  COMPUTE_Q(P0, 3)
            ISSUE_Q(P0, bn, 2); cp_commit();
        } else {
            // tail: no more issues; ladder the waits so each quarter is fenced
            cp_wait2();  COMPUTE_Q(P1, 1)
            cp_wait1();  COMPUTE_Q(P2, 2)
            cp_wait0();  COMPUTE_Q(P0, 3)
        }

        // ---- epilogue: direct STG.64 (each quad = one 32B sector) ----
        float2* og = reinterpret_cast<float2*>(out) + (size_t)b * 32 * 64;
#pragma unroll
        for (int mf = 0; mf < 2; mf++) {
            int r0 = mf * 16 + (lane >> 2);
#pragma unroll
            for (int nt = 0; nt < 8; nt++) {
                int colp = wn * 32 + nt * 4 + (lane & 3);
                og[(size_t)r0 * 64 + colp]       = make_float2(acc[mf][nt][0], acc[mf][nt][1]);
                og[(size_t)(r0 + 8) * 64 + colp] = make_float2(acc[mf][nt][2], acc[mf][nt][3]);
            }
        }

        // rotate slots: next band's q0/q1/q2 live in P1/P2/P0
        float* tmp = P0; P0 = P1; P1 = P2; P2 = tmp;
    }
#undef ISSUE_Q
#undef COMPUTE_Q
}

// ---------------------------------------------------------------------------
extern "C" void kernel_launch(void* const* d_in, const int* in_sizes, int n_in,
                              void* d_out, int out_size) {
    const float* x      = (const float*)d_in[0];
    const float* logits = (const float*)d_in[1];
    const float* u      = (const float*)d_in[2];
    float*       out    = (float*)d_out;

    int dev = 0, sms = 148;
    cudaGetDevice(&dev);
    cudaDeviceGetAttribute(&sms, cudaDevAttrMultiProcessorCount, dev);

    cudaFuncSetAttribute(fused_kernel, cudaFuncAttributeMaxDynamicSharedMemorySize, SMEM_BYTES);

    int rows   = in_sizes[0] / 128;   // 524288
    int nbands = rows / 32;           // 16384
    fused_kernel<<<sms, 384, SMEM_BYTES>>>(x, logits, u, out, nbands);
}